// round 13
// baseline (speedup 1.0000x reference)
#include <cuda_runtime.h>
#include <cuda_bf16.h>
#include <math.h>
#include <stdint.h>

#define HH   1024
#define LL   8192
#define BB   4
#define KDIM 64
#define KTOT 512

#if defined(__CUDA_ARCH_FEAT_SM103_ALL) || defined(__CUDA_ARCH_FEAT_SM100_ALL)
#define HAS_TC 1
#else
#define HAS_TC 0
#endif

// scratch
__device__ float g_filt[HH * KTOT];
__device__ float g_v[(size_t)BB * HH * LL];
__device__ __align__(256) __nv_bfloat16 g_vt[(size_t)BB * LL * 2048]; // [b][l][hi|lo]
__device__ __align__(256) __nv_bfloat16 g_ws[(size_t)HH * 2048];      // [o][hi|lo]
// u split with 512-elem zero halo per (b,h) row: row stride 8704
#define UROW 8704
__device__ __align__(256) __nv_bfloat16 g_uh[(size_t)BB * HH * UROW];
__device__ __align__(256) __nv_bfloat16 g_ul[(size_t)BB * HH * UROW];

// ---------------------------------------------------------------------------
// PTX helpers (guarded)
// ---------------------------------------------------------------------------
#if HAS_TC
__device__ __forceinline__ uint32_t s2u(const void* p) {
    uint32_t a;
    asm("{ .reg .u64 t; cvta.to.shared.u64 t, %1; cvt.u32.u64 %0, t; }"
        : "=r"(a) : "l"(p));
    return a;
}
__device__ __forceinline__ uint32_t elect1() {
    uint32_t p;
    asm volatile("{\n\t.reg .pred p;\n\telect.sync _|p, 0xFFFFFFFF;\n\t"
                 "selp.b32 %0, 1, 0, p;\n\t}" : "=r"(p));
    return p;
}
#define SW128(x) ((x) ^ (((x) >> 3) & 0x70))

static constexpr uint64_t DESC_BASE =
    (2ull << 61) | (1ull << 46) | (64ull << 32) | (1ull << 16); // SW128, LBO=1, SBO=64
__device__ __forceinline__ uint64_t mkdesc(uint32_t a) {
    return DESC_BASE | ((uint64_t)(a >> 4) & 0x3FFF);
}

__device__ __forceinline__ void mma_ss_f16(uint32_t d, uint64_t a, uint64_t b,
                                           uint32_t id, uint32_t en) {
    asm volatile("{\n\t.reg .pred p;\n\tsetp.ne.u32 p, %5, 0;\n\t"
                 "tcgen05.mma.cta_group::1.kind::f16 [%0], %1, %2, %3, {%4,%4,%4,%4}, p;\n\t}"
                 :: "r"(d), "l"(a), "l"(b), "r"(id), "r"(0u), "r"(en) : "memory");
}

#define MBAR_INIT(a, c) \
    asm volatile("mbarrier.init.shared.b64 [%0], %1;" :: "r"(a), "r"(c) : "memory")
#define TC_COMMIT(a) \
    asm volatile("tcgen05.commit.cta_group::1.mbarrier::arrive::one.shared::cluster.b64 [%0];" \
                 :: "r"(a) : "memory")
#define WAIT_PARITY(mb, ph) do {                                              \
    asm volatile("{\n\t.reg .pred P1;\n\t"                                    \
        "WL_%=:\n\t"                                                          \
        "mbarrier.try_wait.parity.acquire.cta.shared::cta.b64 P1, [%0], %1, 0x989680;\n\t" \
        "@P1 bra.uni WD_%=;\n\t"                                              \
        "bra.uni WL_%=;\n\t"                                                  \
        "WD_%=:\n\t}" :: "r"(mb), "r"(ph) : "memory");                        \
} while (0)

#define LDTM_X32(r, a)                                                        \
    asm volatile("tcgen05.ld.sync.aligned.32x32b.x32.b32 "                    \
        "{%0, %1, %2, %3, %4, %5, %6, %7, "                                   \
        " %8, %9, %10, %11, %12, %13, %14, %15, "                             \
        " %16, %17, %18, %19, %20, %21, %22, %23, "                           \
        " %24, %25, %26, %27, %28, %29, %30, %31}, [%32];"                    \
        : "=r"((r)[0]),  "=r"((r)[1]),  "=r"((r)[2]),  "=r"((r)[3]),          \
          "=r"((r)[4]),  "=r"((r)[5]),  "=r"((r)[6]),  "=r"((r)[7]),          \
          "=r"((r)[8]),  "=r"((r)[9]),  "=r"((r)[10]), "=r"((r)[11]),         \
          "=r"((r)[12]), "=r"((r)[13]), "=r"((r)[14]), "=r"((r)[15]),         \
          "=r"((r)[16]), "=r"((r)[17]), "=r"((r)[18]), "=r"((r)[19]),         \
          "=r"((r)[20]), "=r"((r)[21]), "=r"((r)[22]), "=r"((r)[23]),         \
          "=r"((r)[24]), "=r"((r)[25]), "=r"((r)[26]), "=r"((r)[27]),         \
          "=r"((r)[28]), "=r"((r)[29]), "=r"((r)[30]), "=r"((r)[31])          \
        : "r"(a))

#define CPA16(dst, src) \
    asm volatile("cp.async.cg.shared.global [%0], [%1], 16;" \
                 :: "r"(dst), "l"(src) : "memory")
#define CPA_COMMIT() asm volatile("cp.async.commit_group;" ::: "memory")
#define CPA_WAIT(n)  asm volatile("cp.async.wait_group %0;" :: "n"(n) : "memory")
#endif // HAS_TC

// ---------------------------------------------------------------------------
// Kernel 1: assemble multi-scale filter + normalize, AND split W row o = h.
// ---------------------------------------------------------------------------
__global__ void build_filter_kernel(const float* __restrict__ k0,
                                    const float* __restrict__ k1,
                                    const float* __restrict__ k2,
                                    const float* __restrict__ k3,
                                    const float* __restrict__ W) {
    int h   = blockIdx.x;
    int tid = threadIdx.x;             // 128 threads
    const float* ks0 = k0 + h * KDIM;
    const float* ks1 = k1 + h * KDIM;
    const float* ks2 = k2 + h * KDIM;
    const float* ks3 = k3 + h * KDIM;

    #pragma unroll
    for (int rr = 0; rr < 8; rr++) {
        int j = tid + rr * 128;
        float x = W[(size_t)h * HH + j];
        __nv_bfloat16 hi = __float2bfloat16(x);
        __nv_bfloat16 lo = __float2bfloat16(x - __bfloat162float(hi));
        g_ws[(size_t)h * 2048 + j]        = hi;
        g_ws[(size_t)h * 2048 + 1024 + j] = lo;
    }

    __shared__ float red[128];
    float vals[4];
    float ss = 0.0f;

    #pragma unroll
    for (int r = 0; r < 4; r++) {
        int t = tid + r * 128;
        float acc = 0.0f;
        #pragma unroll
        for (int i = 0; i < 4; i++) {
            int Li = KDIM << i;
            if (t < Li) {
                float coord = (t + 0.5f) / (float)(1 << i) - 0.5f;
                coord = fminf(fmaxf(coord, 0.0f), (float)(KDIM - 1));
                int   lo = (int)floorf(coord);
                int   hi = min(lo + 1, KDIM - 1);
                float w  = coord - (float)lo;
                const float* kp = (i == 0) ? ks0 : (i == 1) ? ks1 : (i == 2) ? ks2 : ks3;
                float v = kp[lo] * (1.0f - w) + kp[hi] * w;
                acc += v * (float)(1 << (3 - i));
            }
        }
        vals[r] = acc;
        ss += acc * acc;
    }

    red[tid] = ss;
    __syncthreads();
    for (int s = 64; s > 0; s >>= 1) {
        if (tid < s) red[tid] += red[tid + s];
        __syncthreads();
    }
    float inv = 1.0f / sqrtf(red[0]);

    #pragma unroll
    for (int r = 0; r < 4; r++) {
        int t = tid + r * 128;
        g_filt[h * KTOT + t] = vals[r] * inv;
    }
}

// ---------------------------------------------------------------------------
// Kernel 1b: u -> bf16 hi/lo split with 512-entry zero halo per (b,h) row
// ---------------------------------------------------------------------------
__global__ __launch_bounds__(256) void usplit_kernel(const float* __restrict__ u) {
    int bh  = blockIdx.x;               // 0..4095
    int tid = threadIdx.x;
    size_t src = (size_t)bh * LL;
    size_t dst = (size_t)bh * UROW;

    if (tid < 256) {
        ((uint32_t*)(g_uh + dst))[tid] = 0u;
        ((uint32_t*)(g_ul + dst))[tid] = 0u;
    }
    #pragma unroll
    for (int i = 0; i < 16; i++) {
        int l2 = (tid + i * 256) * 2;
        float2 x = *reinterpret_cast<const float2*>(u + src + l2);
        __nv_bfloat16 h0 = __float2bfloat16(x.x);
        __nv_bfloat16 l0 = __float2bfloat16(x.x - __bfloat162float(h0));
        __nv_bfloat16 h1 = __float2bfloat16(x.y);
        __nv_bfloat16 l1 = __float2bfloat16(x.y - __bfloat162float(h1));
        uint32_t ph = (uint32_t)*(uint16_t*)&h0 | ((uint32_t)*(uint16_t*)&h1 << 16);
        uint32_t pl = (uint32_t)*(uint16_t*)&l0 | ((uint32_t)*(uint16_t*)&l1 << 16);
        *(uint32_t*)(g_uh + dst + 512 + l2) = ph;
        *(uint32_t*)(g_ul + dst + 512 + l2) = pl;
    }
}

// ---------------------------------------------------------------------------
// Kernel 2: Toeplitz FIR on tensor cores — N=256, segment-major chunks.
// grid (1024): one CTA per head. D[i=128, n'=256], 30 chunks of GK=64:
//   seg 0 (c 0-9):  A=T_hi, B=U_hi    seg 1 (c 10-19): A=T_hi, B=U_lo
//   seg 2 (c 20-29): A=T_lo, B=U_hi
// 4-stage 48KB ring (A 16KB + B 32KB), identical structure to gemm ring.
// ---------------------------------------------------------------------------
#define TSTG    0xC000               // 48KB per stage
#define TB_OFF  0x4000               // B (U) offset within stage
#define TKR     (4 * TSTG)           // kr arrays base (0x30000)
#define TKF     (TKR + 0x1800)       // fp32 filter copy (2KB)
#define TMB     (TKR + 0x2000)       // 4 mbarriers
#define TTM     (TKR + 0x2040)       // tmem ptr
#define SMEM_TOTAL_T (TKR + 0x2080)
#define NCHT    30

#if HAS_TC
static constexpr uint32_t IDESC_T =
    (1u << 4) | (1u << 7) | (1u << 10) | ((256 / 8) << 17) | ((128 / 16) << 24);
#endif

__global__ void __launch_bounds__(256, 1)
toeplitz_fir_kernel(const float* __restrict__ u, const float* __restrict__ D) {
    extern __shared__ char smem[];
    int tid = threadIdx.x;
    int h   = blockIdx.x;               // 0..1023

#if HAS_TC
    uint32_t sb = s2u(smem);
    int wid  = tid >> 5;
    int lane = tid & 31;

    if (wid == 0) {
        asm volatile("tcgen05.alloc.cta_group::1.sync.aligned.shared::cta.b32 [%0], %1;"
                     :: "r"(sb + TTM), "r"(256) : "memory");
    }
    if (tid == 0) {
        #pragma unroll
        for (int s = 0; s < 4; s++) MBAR_INIT(sb + TMB + s * 8, 1);
    }

    // filter fp32 copy
    float* kf = (float*)(smem + TKF);
    if (tid < 128) {
        *reinterpret_cast<float4*>(kf + tid * 4) =
            *reinterpret_cast<const float4*>(g_filt + h * KTOT + tid * 4);
    }
    __syncthreads();

    // kr[x], x in [0,768): (x in [128,640)) ? k[639-x] : 0 ; two alignments
    __nv_bfloat16* kr0h = (__nv_bfloat16*)(smem + TKR);
    __nv_bfloat16* kr0l = (__nv_bfloat16*)(smem + TKR + 0x600);
    __nv_bfloat16* kr1h = (__nv_bfloat16*)(smem + TKR + 0xC00);
    __nv_bfloat16* kr1l = (__nv_bfloat16*)(smem + TKR + 0x1200);
    for (int x = tid; x < 768; x += 256) {
        float v = (x >= 128 && x < 640) ? kf[639 - x] : 0.0f;
        __nv_bfloat16 hi = __float2bfloat16(v);
        __nv_bfloat16 lo = __float2bfloat16(v - __bfloat162float(hi));
        kr0h[x] = hi; kr0l[x] = lo;
    }
    __syncthreads();
    for (int x = tid; x < 768; x += 256) {
        __nv_bfloat16 z; *(uint16_t*)&z = 0;
        kr1h[x] = (x + 1 < 768) ? kr0h[x + 1] : z;
        kr1l[x] = (x + 1 < 768) ? kr0l[x + 1] : z;
    }
    __syncthreads();

    uint32_t tmem;
    asm volatile("ld.shared.b32 %0, [%1];" : "=r"(tmem) : "r"(sb + TTM));

    // per-thread geometry
    // T fill: 2 threads per row; U fill: 1 thread per row (256 rows)
    int ti  = tid >> 1;                 // T row i 0..127
    int tjb = (tid & 1) * 32;           // T col base
    int un  = tid;                      // U row n' 0..255
    int ubb = un >> 6;
    int utl = un & 63;
    size_t urow = ((size_t)(ubb * HH + h)) * UROW + utl * 128;

    const uint32_t* kr0h32 = (const uint32_t*)kr0h;
    const uint32_t* kr0l32 = (const uint32_t*)kr0l;
    const uint32_t* kr1h32 = (const uint32_t*)kr1h;
    const uint32_t* kr1l32 = (const uint32_t*)kr1l;

#define FILL_CHUNK(c, s)                                                      \
    do {                                                                      \
        int seg = (c) / 10;                                                   \
        int kc  = (c) - seg * 10;        /* 0..9 */                           \
        /* U (B) via cp.async */                                              \
        const __nv_bfloat16* srcu = ((seg == 1) ? g_ul : g_uh) + urow + 64 * kc; \
        uint32_t bd = sb + (s) * TSTG + TB_OFF;                               \
        _Pragma("unroll")                                                     \
        for (int q = 0; q < 8; q++)                                           \
            CPA16(bd + SW128(un * 128 + q * 16), srcu + q * 8);               \
        /* T (A) build from kr */                                             \
        const uint32_t* s0 = (seg == 2) ? kr0l32 : kr0h32;                    \
        const uint32_t* s1 = (seg == 2) ? kr1l32 : kr1h32;                    \
        uint32_t ad = sb + (s) * TSTG;                                        \
        _Pragma("unroll")                                                     \
        for (int o = 0; o < 4; o++) {                                         \
            int js0 = tjb + 8 * o;                                            \
            int x0  = 128 + js0 + 64 * kc - ti - 1;                           \
            const uint32_t* sp;                                               \
            int w;                                                            \
            if (x0 & 1) { w = (x0 - 1) >> 1; sp = s1 + w; }                   \
            else        { w = x0 >> 1;       sp = s0 + w; }                   \
            uint4 vv = make_uint4(sp[0], sp[1], sp[2], sp[3]);                \
            *(uint4*)(smem + (s) * TSTG + SW128(ti * 128 + js0 * 2)) = vv;    \
        }                                                                     \
        (void)ad;                                                             \
    } while (0)

    FILL_CHUNK(0, 0); CPA_COMMIT();
    FILL_CHUNK(1, 1); CPA_COMMIT();
    CPA_WAIT(0);
    asm volatile("fence.proxy.async.shared::cta;" ::: "memory");
    __syncthreads();

    uint32_t ph[4] = {0, 0, 0, 0};

    for (int c = 0; c < NCHT; c++) {
        int s = c & 3;
        if (wid == 0) {
            if (elect1()) {
                uint64_t aD = mkdesc(sb + s * TSTG);
                uint64_t bD = mkdesc(sb + s * TSTG + TB_OFF);
                #pragma unroll
                for (int k = 0; k < 4; k++)
                    mma_ss_f16(tmem, aD + k * 2, bD + k * 2, IDESC_T,
                               (c > 0 || k > 0) ? 1u : 0u);
                TC_COMMIT(sb + TMB + s * 8);
            }
        }
        if (c + 2 < NCHT) {
            int ws = (c + 2) & 3;
            if (c >= 2) {
                WAIT_PARITY(sb + TMB + ws * 8, ph[ws]);
                ph[ws] ^= 1;
            }
            FILL_CHUNK(c + 2, ws);
            CPA_COMMIT();
            CPA_WAIT(1);
        } else {
            CPA_WAIT(0);
        }
        asm volatile("fence.proxy.async.shared::cta;" ::: "memory");
        __syncthreads();
    }
    // last chunk 29 -> stage 1
    WAIT_PARITY(sb + TMB + 1 * 8, ph[1]);
    asm volatile("tcgen05.fence::after_thread_sync;" ::: "memory");

    // epilogue: lanes = i (l within tile), cols = n' = (b,tile)
    float Dh = D[h];
    const float iS2 = 0.70710678118654752440f;
    int sub   = wid & 3;
    int chalf = wid >> 2;
    int il    = sub * 32 + lane;
    #pragma unroll
    for (int it = 0; it < 4; it++) {
        int cb = chalf * 128 + it * 32;
        uint32_t r[32];
        LDTM_X32(r, tmem + cb);
        asm volatile("tcgen05.wait::ld.sync.aligned;" ::: "memory");
        #pragma unroll
        for (int j = 0; j < 32; j++) {
            int nn = cb + j;
            int bb = nn >> 6;
            int tl = nn & 63;
            int l  = tl * 128 + il;
            size_t off = ((size_t)(bb * HH + h)) * LL + l;
            float x = __uint_as_float(r[j]) + Dh * u[off];
            g_v[off] = 0.5f * x * (1.0f + erff(x * iS2));
        }
    }
    __syncthreads();
    if (wid == 0) {
        asm volatile("tcgen05.relinquish_alloc_permit.cta_group::1.sync.aligned;");
        asm volatile("tcgen05.dealloc.cta_group::1.sync.aligned.b32 %0, %1;"
                     :: "r"(tmem), "r"(256));
    }
#undef FILL_CHUNK

#else  // naive fallback (baseline-family cubin; not used on sm_103a)
    float Dh = D[h];
    const float iS2 = 0.70710678118654752440f;
    for (int idx = tid; idx < 256 * 128; idx += 256) {
        int np = idx >> 7;
        int i  = idx & 127;
        int bb = np >> 6;
        int tl = np & 63;
        int l  = tl * 128 + i;
        const float* up = u + ((size_t)(bb * HH + h)) * LL;
        float acc = 0.0f;
        for (int t = 0; t < KTOT; t++) {
            int li = l - t;
            if (li >= 0) acc += g_filt[h * KTOT + t] * up[li];
        }
        float x = acc + Dh * up[l];
        g_v[((size_t)(bb * HH + h)) * LL + l] = 0.5f * x * (1.0f + erff(x * iS2));
    }
#endif
}

// ---------------------------------------------------------------------------
// Kernel 2b: transpose + bf16 hi/lo split: g_v[b][h][l] -> g_vt[b][l][hi|lo]
// ---------------------------------------------------------------------------
__global__ __launch_bounds__(256) void transpose_split_kernel() {
    __shared__ float ts[64][65];
    int l0 = blockIdx.x * 64;
    int h0 = blockIdx.y * 64;
    int b  = blockIdx.z;
    int t  = threadIdx.x;
    int tl = t & 63;
    int tr = t >> 6;

    const float* vp = g_v + ((size_t)(b * HH + h0)) * LL + l0;
    #pragma unroll
    for (int i = 0; i < 16; i++) {
        int hh = tr + i * 4;
        ts[hh][tl] = vp[(size_t)hh * LL + tl];
    }
    __syncthreads();

    __nv_bfloat16* op = g_vt + ((size_t)b * LL + l0) * 2048;
    #pragma unroll
    for (int i = 0; i < 16; i++) {
        int ll = tr + i * 4;
        float x = ts[tl][ll];
        __nv_bfloat16 hi = __float2bfloat16(x);
        __nv_bfloat16 lo = __float2bfloat16(x - __bfloat162float(hi));
        op[(size_t)ll * 2048 + h0 + tl]        = hi;
        op[(size_t)ll * 2048 + 1024 + h0 + tl] = lo;
    }
}

// ---------------------------------------------------------------------------
// Kernel 3: tcgen05 split-bf16 GEMM, 4-stage ring, cp.async mainloop. PROVEN.
// ---------------------------------------------------------------------------
#define GM     128
#define GN     256
#define GK     64
#define NCHUNK 48
#define NSTG   4
#define STGSZ  (48 * 1024)
#define SBOFF  (16 * 1024)

#define SMB   (NSTG * STGSZ)
#define STM   (NSTG * STGSZ + 64)
#define SBIAS (NSTG * STGSZ + 128)
#define SMEM_TOTAL_G (NSTG * STGSZ + 128 + 1024)

#if HAS_TC
static constexpr uint32_t IDESC =
    (1u << 4) | (1u << 7) | (1u << 10) | ((GN / 8) << 17) | ((GM / 16) << 24);
#endif

__global__ void __launch_bounds__(256, 1)
gemm_kernel(const float* __restrict__ bias, float* __restrict__ out,
            const float* __restrict__ W) {
    extern __shared__ char smem[];
    int tid  = threadIdx.x;
    int l0 = blockIdx.x * GM;
    int o0 = blockIdx.y * GN;
    int b  = blockIdx.z;

#if HAS_TC
    uint32_t sb = s2u(smem);
    int wid  = tid >> 5;
    int lane = tid & 31;

    if (wid == 0) {
        asm volatile("tcgen05.alloc.cta_group::1.sync.aligned.shared::cta.b32 [%0], %1;"
                     :: "r"(sb + STM), "r"(256) : "memory");
    }
    if (tid == 0) {
        #pragma unroll
        for (int s = 0; s < NSTG; s++) MBAR_INIT(sb + SMB + s * 8, 1);
    }
    ((float*)(smem + SBIAS))[tid] = bias[o0 + tid];
    __syncthreads();
    uint32_t tmem;
    asm volatile("ld.shared.b32 %0, [%1];" : "=r"(tmem) : "r"(sb + STM));

    const __nv_bfloat16* vt = g_vt + (size_t)b * LL * 2048;

    int ar = tid >> 3, aq = tid & 7;

#define CPA_CHUNK(c, s)                                                       \
    do {                                                                      \
        int seg  = (c) >> 4;                                                  \
        int kc   = ((c) & 15) * GK;                                           \
        int aoff = (seg == 1) ? 1024 : 0;                                     \
        int boff = (seg == 2) ? 1024 : 0;                                     \
        const __nv_bfloat16* ap = vt + (size_t)l0 * 2048 + aoff + kc;         \
        const __nv_bfloat16* bp = g_ws + (size_t)o0 * 2048 + boff + kc;       \
        uint32_t As = sb + (s) * STGSZ;                                       \
        uint32_t Bs = As + SBOFF;                                             \
        _Pragma("unroll")                                                     \
        for (int i = 0; i < 4; i++) {                                         \
            int r = ar + i * 32;                                              \
            CPA16(As + SW128(r * 128 + aq * 16),                              \
                  ap + (size_t)r * 2048 + aq * 8);                            \
        }                                                                     \
        _Pragma("unroll")                                                     \
        for (int i = 0; i < 8; i++) {                                         \
            int r = ar + i * 32;                                              \
            CPA16(Bs + SW128(r * 128 + aq * 16),                              \
                  bp + (size_t)r * 2048 + aq * 8);                            \
        }                                                                     \
    } while (0)

    CPA_CHUNK(0, 0); CPA_COMMIT();
    CPA_CHUNK(1, 1); CPA_COMMIT();
    CPA_WAIT(0);
    asm volatile("fence.proxy.async.shared::cta;" ::: "memory");
    __syncthreads();

    uint32_t ph[NSTG] = {0, 0, 0, 0};

    for (int c = 0; c < NCHUNK; c++) {
        int s = c & (NSTG - 1);
        if (wid == 0) {
            if (elect1()) {
                uint64_t ad = mkdesc(sb + s * STGSZ);
                uint64_t bd = mkdesc(sb + s * STGSZ + SBOFF);
                #pragma unroll
                for (int k = 0; k < 4; k++)
                    mma_ss_f16(tmem, ad + k * 2, bd + k * 2, IDESC,
                               (c > 0 || k > 0) ? 1u : 0u);
                TC_COMMIT(sb + SMB + s * 8);
            }
        }
        if (c + 2 < NCHUNK) {
            int ws = (c + 2) & (NSTG - 1);
            if (c >= 2) {
                WAIT_PARITY(sb + SMB + ws * 8, ph[ws]);
                ph[ws] ^= 1;
            }
            CPA_CHUNK(c + 2, ws);
            CPA_COMMIT();
            CPA_WAIT(1);
        } else {
            CPA_WAIT(0);
        }
        asm volatile("fence.proxy.async.shared::cta;" ::: "memory");
        __syncthreads();
    }
    WAIT_PARITY(sb + SMB + 3 * 8, ph[3]);
    asm volatile("tcgen05.fence::after_thread_sync;" ::: "memory");

    int sub  = wid & 3;
    int half = wid >> 2;
    int lg   = l0 + sub * 32 + lane;
    const float* bs = (const float*)(smem + SBIAS);
    #pragma unroll
    for (int it = 0; it < 4; it++) {
        int cb = half * 128 + it * 32;
        uint32_t r[32];
        LDTM_X32(r, tmem + cb);
        asm volatile("tcgen05.wait::ld.sync.aligned;" ::: "memory");
        float* op = out + ((size_t)(b * HH + o0 + cb)) * LL + lg;
        #pragma unroll
        for (int j = 0; j < 32; j++)
            op[(size_t)j * LL] = __uint_as_float(r[j]) + bs[cb + j];
    }
    __syncthreads();
    if (wid == 0) {
        asm volatile("tcgen05.relinquish_alloc_permit.cta_group::1.sync.aligned;");
        asm volatile("tcgen05.dealloc.cta_group::1.sync.aligned.b32 %0, %1;"
                     :: "r"(tmem), "r"(256));
    }
#undef CPA_CHUNK

#else  // SIMT fp32 fallback
    float (*Ws)[GN]  = (float (*)[GN])(smem);
    float (*Vs)[128] = (float (*)[128])(smem + 16 * GN * 4);

    int tx = tid & 15;
    int ty = tid >> 4;

    float acc[16][8];
    #pragma unroll
    for (int i = 0; i < 16; i++)
        #pragma unroll
        for (int j = 0; j < 8; j++) acc[i][j] = 0.0f;

    const float* vbase = g_v + ((size_t)b * HH) * LL + l0;

    for (int kb = 0; kb < HH; kb += 16) {
        #pragma unroll
        for (int i = 0; i < 16; i++) {
            int idx = tid + i * 256;
            int kk  = idx & 15;
            int mm  = idx >> 4;
            Ws[kk][mm] = W[(size_t)(o0 + mm) * HH + kb + kk];
        }
        #pragma unroll
        for (int i = 0; i < 8; i++) {
            int idx = tid + i * 256;
            int ll  = idx & 127;
            int kk  = idx >> 7;
            Vs[kk][ll] = vbase[(size_t)(kb + kk) * LL + ll];
        }
        __syncthreads();

        #pragma unroll
        for (int kk = 0; kk < 16; kk++) {
            float bf[8];
            #pragma unroll
            for (int j = 0; j < 8; j++) bf[j] = Vs[kk][tx * 8 + j];
            #pragma unroll
            for (int i = 0; i < 16; i++) {
                float a = Ws[kk][ty * 16 + i];
                #pragma unroll
                for (int j = 0; j < 8; j++)
                    acc[i][j] += a * bf[j];
            }
        }
        __syncthreads();
    }

    #pragma unroll
    for (int i = 0; i < 16; i++) {
        int o = o0 + ty * 16 + i;
        float bb = bias[o];
        float* op = out + ((size_t)(b * HH + o)) * LL + l0 + tx * 8;
        #pragma unroll
        for (int j = 0; j < 8; j++)
            op[j] = acc[i][j] + bb;
    }
#endif
}

// ---------------------------------------------------------------------------
extern "C" void kernel_launch(void* const* d_in, const int* in_sizes, int n_in,
                              void* d_out, int out_size) {
    const float* u  = (const float*)d_in[0];
    const float* k0 = (const float*)d_in[1];
    const float* k1 = (const float*)d_in[2];
    const float* k2 = (const float*)d_in[3];
    const float* k3 = (const float*)d_in[4];
    const float* D  = (const float*)d_in[5];
    const float* W  = (const float*)d_in[6];
    const float* b  = (const float*)d_in[7];
    float* out = (float*)d_out;

    build_filter_kernel<<<HH, 128>>>(k0, k1, k2, k3, W);

    usplit_kernel<<<BB * HH, 256>>>(u);

    cudaFuncSetAttribute(toeplitz_fir_kernel,
                         cudaFuncAttributeMaxDynamicSharedMemorySize, SMEM_TOTAL_T);
    toeplitz_fir_kernel<<<HH, 256, SMEM_TOTAL_T>>>(u, D);

    dim3 gt(LL / 64, HH / 64, BB);
    transpose_split_kernel<<<gt, 256>>>();

    cudaFuncSetAttribute(gemm_kernel, cudaFuncAttributeMaxDynamicSharedMemorySize,
                         SMEM_TOTAL_G);
    dim3 g3(LL / GM, HH / GN, BB);
    gemm_kernel<<<g3, 256, SMEM_TOTAL_G>>>(b, out, W);
}

// round 14
// speedup vs baseline: 1.1950x; 1.1950x over previous
#include <cuda_runtime.h>
#include <cuda_bf16.h>
#include <math.h>
#include <stdint.h>

#define HH   1024
#define LL   8192
#define BB   4
#define KDIM 64
#define KTOT 512

#if defined(__CUDA_ARCH_FEAT_SM103_ALL) || defined(__CUDA_ARCH_FEAT_SM100_ALL)
#define HAS_TC 1
#else
#define HAS_TC 0
#endif

// scratch
__device__ float g_filt[HH * KTOT];
__device__ float g_v[(size_t)BB * HH * LL];
__device__ __align__(256) __nv_bfloat16 g_vt[(size_t)BB * LL * 2048]; // [b][l][hi|lo]
__device__ __align__(256) __nv_bfloat16 g_ws[(size_t)HH * 2048];      // [o][hi|lo]
// u split with 512-elem zero halo per (b,h) row: row stride 8704
#define UROW 8704
__device__ __align__(256) __nv_bfloat16 g_uh[(size_t)BB * HH * UROW];
__device__ __align__(256) __nv_bfloat16 g_ul[(size_t)BB * HH * UROW];

// ---------------------------------------------------------------------------
// PTX helpers (guarded)
// ---------------------------------------------------------------------------
#if HAS_TC
__device__ __forceinline__ uint32_t s2u(const void* p) {
    uint32_t a;
    asm("{ .reg .u64 t; cvta.to.shared.u64 t, %1; cvt.u32.u64 %0, t; }"
        : "=r"(a) : "l"(p));
    return a;
}
__device__ __forceinline__ uint32_t elect1() {
    uint32_t p;
    asm volatile("{\n\t.reg .pred p;\n\telect.sync _|p, 0xFFFFFFFF;\n\t"
                 "selp.b32 %0, 1, 0, p;\n\t}" : "=r"(p));
    return p;
}
#define SW128(x) ((x) ^ (((x) >> 3) & 0x70))

static constexpr uint64_t DESC_BASE =
    (2ull << 61) | (1ull << 46) | (64ull << 32) | (1ull << 16); // SW128, LBO=1, SBO=64
__device__ __forceinline__ uint64_t mkdesc(uint32_t a) {
    return DESC_BASE | ((uint64_t)(a >> 4) & 0x3FFF);
}

__device__ __forceinline__ void mma_ss_f16(uint32_t d, uint64_t a, uint64_t b,
                                           uint32_t id, uint32_t en) {
    asm volatile("{\n\t.reg .pred p;\n\tsetp.ne.u32 p, %5, 0;\n\t"
                 "tcgen05.mma.cta_group::1.kind::f16 [%0], %1, %2, %3, {%4,%4,%4,%4}, p;\n\t}"
                 :: "r"(d), "l"(a), "l"(b), "r"(id), "r"(0u), "r"(en) : "memory");
}

#define MBAR_INIT(a, c) \
    asm volatile("mbarrier.init.shared.b64 [%0], %1;" :: "r"(a), "r"(c) : "memory")
#define TC_COMMIT(a) \
    asm volatile("tcgen05.commit.cta_group::1.mbarrier::arrive::one.shared::cluster.b64 [%0];" \
                 :: "r"(a) : "memory")
#define WAIT_PARITY(mb, ph) do {                                              \
    asm volatile("{\n\t.reg .pred P1;\n\t"                                    \
        "WL_%=:\n\t"                                                          \
        "mbarrier.try_wait.parity.acquire.cta.shared::cta.b64 P1, [%0], %1, 0x989680;\n\t" \
        "@P1 bra.uni WD_%=;\n\t"                                              \
        "bra.uni WL_%=;\n\t"                                                  \
        "WD_%=:\n\t}" :: "r"(mb), "r"(ph) : "memory");                        \
} while (0)

#define LDTM_X32(r, a)                                                        \
    asm volatile("tcgen05.ld.sync.aligned.32x32b.x32.b32 "                    \
        "{%0, %1, %2, %3, %4, %5, %6, %7, "                                   \
        " %8, %9, %10, %11, %12, %13, %14, %15, "                             \
        " %16, %17, %18, %19, %20, %21, %22, %23, "                           \
        " %24, %25, %26, %27, %28, %29, %30, %31}, [%32];"                    \
        : "=r"((r)[0]),  "=r"((r)[1]),  "=r"((r)[2]),  "=r"((r)[3]),          \
          "=r"((r)[4]),  "=r"((r)[5]),  "=r"((r)[6]),  "=r"((r)[7]),          \
          "=r"((r)[8]),  "=r"((r)[9]),  "=r"((r)[10]), "=r"((r)[11]),         \
          "=r"((r)[12]), "=r"((r)[13]), "=r"((r)[14]), "=r"((r)[15]),         \
          "=r"((r)[16]), "=r"((r)[17]), "=r"((r)[18]), "=r"((r)[19]),         \
          "=r"((r)[20]), "=r"((r)[21]), "=r"((r)[22]), "=r"((r)[23]),         \
          "=r"((r)[24]), "=r"((r)[25]), "=r"((r)[26]), "=r"((r)[27]),         \
          "=r"((r)[28]), "=r"((r)[29]), "=r"((r)[30]), "=r"((r)[31])          \
        : "r"(a))

#define CPA16(dst, src) \
    asm volatile("cp.async.cg.shared.global [%0], [%1], 16;" \
                 :: "r"(dst), "l"(src) : "memory")
#define CPA_COMMIT() asm volatile("cp.async.commit_group;" ::: "memory")
#define CPA_WAIT(n)  asm volatile("cp.async.wait_group %0;" :: "n"(n) : "memory")
#endif // HAS_TC

// ---------------------------------------------------------------------------
// Kernel 1: assemble multi-scale filter + normalize, AND split W row o = h.
// ---------------------------------------------------------------------------
__global__ void build_filter_kernel(const float* __restrict__ k0,
                                    const float* __restrict__ k1,
                                    const float* __restrict__ k2,
                                    const float* __restrict__ k3,
                                    const float* __restrict__ W) {
    int h   = blockIdx.x;
    int tid = threadIdx.x;             // 128 threads
    const float* ks0 = k0 + h * KDIM;
    const float* ks1 = k1 + h * KDIM;
    const float* ks2 = k2 + h * KDIM;
    const float* ks3 = k3 + h * KDIM;

    #pragma unroll
    for (int rr = 0; rr < 8; rr++) {
        int j = tid + rr * 128;
        float x = W[(size_t)h * HH + j];
        __nv_bfloat16 hi = __float2bfloat16(x);
        __nv_bfloat16 lo = __float2bfloat16(x - __bfloat162float(hi));
        g_ws[(size_t)h * 2048 + j]        = hi;
        g_ws[(size_t)h * 2048 + 1024 + j] = lo;
    }

    __shared__ float red[128];
    float vals[4];
    float ss = 0.0f;

    #pragma unroll
    for (int r = 0; r < 4; r++) {
        int t = tid + r * 128;
        float acc = 0.0f;
        #pragma unroll
        for (int i = 0; i < 4; i++) {
            int Li = KDIM << i;
            if (t < Li) {
                float coord = (t + 0.5f) / (float)(1 << i) - 0.5f;
                coord = fminf(fmaxf(coord, 0.0f), (float)(KDIM - 1));
                int   lo = (int)floorf(coord);
                int   hi = min(lo + 1, KDIM - 1);
                float w  = coord - (float)lo;
                const float* kp = (i == 0) ? ks0 : (i == 1) ? ks1 : (i == 2) ? ks2 : ks3;
                float v = kp[lo] * (1.0f - w) + kp[hi] * w;
                acc += v * (float)(1 << (3 - i));
            }
        }
        vals[r] = acc;
        ss += acc * acc;
    }

    red[tid] = ss;
    __syncthreads();
    for (int s = 64; s > 0; s >>= 1) {
        if (tid < s) red[tid] += red[tid + s];
        __syncthreads();
    }
    float inv = 1.0f / sqrtf(red[0]);

    #pragma unroll
    for (int r = 0; r < 4; r++) {
        int t = tid + r * 128;
        g_filt[h * KTOT + t] = vals[r] * inv;
    }
}

// ---------------------------------------------------------------------------
// Kernel 1b: u -> bf16 hi/lo split with 512-entry zero halo per (b,h) row
// ---------------------------------------------------------------------------
__global__ __launch_bounds__(256) void usplit_kernel(const float* __restrict__ u) {
    int bh  = blockIdx.x;               // 0..4095
    int tid = threadIdx.x;
    size_t src = (size_t)bh * LL;
    size_t dst = (size_t)bh * UROW;

    if (tid < 256) {
        ((uint32_t*)(g_uh + dst))[tid] = 0u;
        ((uint32_t*)(g_ul + dst))[tid] = 0u;
    }
    #pragma unroll
    for (int i = 0; i < 16; i++) {
        int l2 = (tid + i * 256) * 2;
        float2 x = *reinterpret_cast<const float2*>(u + src + l2);
        __nv_bfloat16 h0 = __float2bfloat16(x.x);
        __nv_bfloat16 l0 = __float2bfloat16(x.x - __bfloat162float(h0));
        __nv_bfloat16 h1 = __float2bfloat16(x.y);
        __nv_bfloat16 l1 = __float2bfloat16(x.y - __bfloat162float(h1));
        uint32_t ph = (uint32_t)*(uint16_t*)&h0 | ((uint32_t)*(uint16_t*)&h1 << 16);
        uint32_t pl = (uint32_t)*(uint16_t*)&l0 | ((uint32_t)*(uint16_t*)&l1 << 16);
        *(uint32_t*)(g_uh + dst + 512 + l2) = ph;
        *(uint32_t*)(g_ul + dst + 512 + l2) = pl;
    }
}

// ---------------------------------------------------------------------------
// Kernel 2: Toeplitz FIR on tensor cores (ROUND-12 PROVEN VERSION).
// grid (nh=2, h=1024). Per CTA: D[i=128, n'=128] = sum_j T[i,j]*U[n',j],
// K=640 in 10 chunks of 64; T[i,j]=kr[j-i-1] built in smem from the filter;
// U = overlapping u slices (halo-padded bf16 hi/lo), cp.async loaded.
// 3 split segments per chunk: (T_hi,U_hi),(T_hi,U_lo),(T_lo,U_hi).
// Epilogue: + D[h]*u (exact fp32), exact gelu -> g_v (coalesced).
// ---------------------------------------------------------------------------
#define TSTG    0x10000              // 64KB per stage
#define TH_OFF  0
#define TL_OFF  0x4000
#define UH_OFF  0x8000
#define UL_OFF  0xC000
#define TKR     (3 * TSTG)           // kr arrays base
#define TKF     (TKR + 0x1800)       // fp32 filter copy (2KB)
#define TMB     (TKR + 0x2000)       // 3 mbarriers
#define TTM     (TKR + 0x2040)       // tmem ptr
#define SMEM_TOTAL_T (TKR + 0x2080)

#if HAS_TC
static constexpr uint32_t IDESC_T =
    (1u << 4) | (1u << 7) | (1u << 10) | ((128 / 8) << 17) | ((128 / 16) << 24);
#endif

__global__ void __launch_bounds__(256, 1)
toeplitz_fir_kernel(const float* __restrict__ u, const float* __restrict__ D) {
    extern __shared__ char smem[];
    int tid = threadIdx.x;
    int nh  = blockIdx.x;               // 0..1  (n half)
    int h   = blockIdx.y;               // 0..1023

#if HAS_TC
    uint32_t sb = s2u(smem);
    int wid  = tid >> 5;
    int lane = tid & 31;

    if (wid == 0) {
        asm volatile("tcgen05.alloc.cta_group::1.sync.aligned.shared::cta.b32 [%0], %1;"
                     :: "r"(sb + TTM), "r"(128) : "memory");
    }
    if (tid == 0) {
        #pragma unroll
        for (int s = 0; s < 3; s++) MBAR_INIT(sb + TMB + s * 8, 1);
    }

    // filter fp32 copy
    float* kf = (float*)(smem + TKF);
    if (tid < 128) {
        *reinterpret_cast<float4*>(kf + tid * 4) =
            *reinterpret_cast<const float4*>(g_filt + h * KTOT + tid * 4);
    }
    __syncthreads();

    // kr storage: kr[x] (x in [0,768)) = (x in [128,640)) ? k[639-x] : 0
    // two shift-aligned copies per precision (for odd/even 16B gathers)
    __nv_bfloat16* kr0h = (__nv_bfloat16*)(smem + TKR);
    __nv_bfloat16* kr0l = (__nv_bfloat16*)(smem + TKR + 0x600);
    __nv_bfloat16* kr1h = (__nv_bfloat16*)(smem + TKR + 0xC00);
    __nv_bfloat16* kr1l = (__nv_bfloat16*)(smem + TKR + 0x1200);
    for (int x = tid; x < 768; x += 256) {
        float v = (x >= 128 && x < 640) ? kf[639 - x] : 0.0f;
        __nv_bfloat16 hi = __float2bfloat16(v);
        __nv_bfloat16 lo = __float2bfloat16(v - __bfloat162float(hi));
        kr0h[x] = hi; kr0l[x] = lo;
    }
    __syncthreads();
    for (int x = tid; x < 768; x += 256) {
        __nv_bfloat16 z; *(uint16_t*)&z = 0;
        kr1h[x] = (x + 1 < 768) ? kr0h[x + 1] : z;
        kr1l[x] = (x + 1 < 768) ? kr0l[x + 1] : z;
    }
    __syncthreads();

    uint32_t tmem;
    asm volatile("ld.shared.b32 %0, [%1];" : "=r"(tmem) : "r"(sb + TTM));

    // per-thread fill geometry
    int un  = tid >> 1;                 // U row n' 0..127
    int uq  = (tid & 1) * 4;            // 4 of 8 octets
    int nng = nh * 128 + un;
    int ubb = nng >> 6;
    int utl = nng & 63;
    size_t urow = ((size_t)(ubb * HH + h)) * UROW + utl * 128;
    int ti = tid >> 1;                  // T row i 0..127
    int tjb = (tid & 1) * 32;           // T col base

    const uint32_t* kr0h32 = (const uint32_t*)kr0h;
    const uint32_t* kr0l32 = (const uint32_t*)kr0l;
    const uint32_t* kr1h32 = (const uint32_t*)kr1h;
    const uint32_t* kr1l32 = (const uint32_t*)kr1l;

#define FILL_CHUNK(c, s)                                                      \
    do {                                                                      \
        /* U via cp.async */                                                  \
        const __nv_bfloat16* srh = g_uh + urow + 64 * (c);                    \
        const __nv_bfloat16* srl = g_ul + urow + 64 * (c);                    \
        uint32_t uhd = sb + (s) * TSTG + UH_OFF;                              \
        uint32_t uld = sb + (s) * TSTG + UL_OFF;                              \
        _Pragma("unroll")                                                     \
        for (int q = 0; q < 4; q++) {                                         \
            uint32_t so = SW128(un * 128 + (uq + q) * 16);                    \
            CPA16(uhd + so, srh + (uq + q) * 8);                              \
            CPA16(uld + so, srl + (uq + q) * 8);                              \
        }                                                                     \
        /* T build from kr */                                                 \
        uint32_t thd = sb + (s) * TSTG + TH_OFF;                              \
        uint32_t tld = sb + (s) * TSTG + TL_OFF;                              \
        _Pragma("unroll")                                                     \
        for (int o = 0; o < 4; o++) {                                         \
            int js0 = tjb + 8 * o;                                            \
            int x0  = 128 + js0 + 64 * (c) - ti - 1;                          \
            const uint32_t* sh; const uint32_t* sl;                           \
            if (x0 & 1) { int w = (x0 - 1) >> 1; sh = kr1h32 + w; sl = kr1l32 + w; } \
            else        { int w = x0 >> 1;       sh = kr0h32 + w; sl = kr0l32 + w; } \
            uint4 vh = make_uint4(sh[0], sh[1], sh[2], sh[3]);                \
            uint4 vl = make_uint4(sl[0], sl[1], sl[2], sl[3]);                \
            uint32_t dsto = SW128(ti * 128 + js0 * 2);                        \
            *(uint4*)(smem + (thd - sb) + dsto) = vh;                         \
            *(uint4*)(smem + (tld - sb) + dsto) = vl;                         \
        }                                                                     \
    } while (0)

    FILL_CHUNK(0, 0); CPA_COMMIT();
    FILL_CHUNK(1, 1); CPA_COMMIT();
    CPA_WAIT(0);
    asm volatile("fence.proxy.async.shared::cta;" ::: "memory");
    __syncthreads();

    uint32_t ph[3] = {0, 0, 0};

    for (int c = 0; c < 10; c++) {
        int s = c - (c / 3) * 3;
        if (wid == 0) {
            if (elect1()) {
                uint64_t ThD = mkdesc(sb + s * TSTG + TH_OFF);
                uint64_t TlD = mkdesc(sb + s * TSTG + TL_OFF);
                uint64_t UhD = mkdesc(sb + s * TSTG + UH_OFF);
                uint64_t UlD = mkdesc(sb + s * TSTG + UL_OFF);
                #pragma unroll
                for (int k = 0; k < 4; k++)
                    mma_ss_f16(tmem, ThD + k * 2, UhD + k * 2, IDESC_T,
                               (c > 0 || k > 0) ? 1u : 0u);
                #pragma unroll
                for (int k = 0; k < 4; k++)
                    mma_ss_f16(tmem, ThD + k * 2, UlD + k * 2, IDESC_T, 1u);
                #pragma unroll
                for (int k = 0; k < 4; k++)
                    mma_ss_f16(tmem, TlD + k * 2, UhD + k * 2, IDESC_T, 1u);
                TC_COMMIT(sb + TMB + s * 8);
            }
        }
        if (c + 2 < 10) {
            int ws = (c + 2) - ((c + 2) / 3) * 3;
            if (c >= 1) {
                WAIT_PARITY(sb + TMB + ws * 8, ph[ws]);
                ph[ws] ^= 1;
            }
            FILL_CHUNK(c + 2, ws);
            CPA_COMMIT();
            CPA_WAIT(1);
        } else {
            CPA_WAIT(0);
        }
        asm volatile("fence.proxy.async.shared::cta;" ::: "memory");
        __syncthreads();
    }
    // last MMA: c=9 -> stage 0
    WAIT_PARITY(sb + TMB + 0 * 8, ph[0]);
    asm volatile("tcgen05.fence::after_thread_sync;" ::: "memory");

    // epilogue: lanes = i (l within tile), cols = n' = (b,tile)
    float Dh = D[h];
    const float iS2 = 0.70710678118654752440f;
    int sub   = wid & 3;
    int chalf = wid >> 2;
    int il    = sub * 32 + lane;
    #pragma unroll
    for (int it = 0; it < 2; it++) {
        int cb = chalf * 64 + it * 32;
        uint32_t r[32];
        LDTM_X32(r, tmem + cb);
        asm volatile("tcgen05.wait::ld.sync.aligned;" ::: "memory");
        #pragma unroll
        for (int j = 0; j < 32; j++) {
            int nn = nh * 128 + cb + j;
            int bb = nn >> 6;
            int tl = nn & 63;
            int l  = tl * 128 + il;
            size_t off = ((size_t)(bb * HH + h)) * LL + l;
            float x = __uint_as_float(r[j]) + Dh * u[off];
            g_v[off] = 0.5f * x * (1.0f + erff(x * iS2));
        }
    }
    __syncthreads();
    if (wid == 0) {
        asm volatile("tcgen05.relinquish_alloc_permit.cta_group::1.sync.aligned;");
        asm volatile("tcgen05.dealloc.cta_group::1.sync.aligned.b32 %0, %1;"
                     :: "r"(tmem), "r"(128));
    }
#undef FILL_CHUNK

#else  // naive fallback (baseline-family cubin; not used on sm_103a)
    float Dh = D[h];
    const float iS2 = 0.70710678118654752440f;
    for (int idx = tid; idx < 128 * 128; idx += 256) {
        int np = idx >> 7;
        int i  = idx & 127;
        int nn = nh * 128 + np;
        int bb = nn >> 6;
        int tl = nn & 63;
        int l  = tl * 128 + i;
        const float* up = u + ((size_t)(bb * HH + h)) * LL;
        float acc = 0.0f;
        for (int t = 0; t < KTOT; t++) {
            int li = l - t;
            if (li >= 0) acc += g_filt[h * KTOT + t] * up[li];
        }
        float x = acc + Dh * up[l];
        g_v[((size_t)(bb * HH + h)) * LL + l] = 0.5f * x * (1.0f + erff(x * iS2));
    }
#endif
}

// ---------------------------------------------------------------------------
// Kernel 2b: transpose + bf16 hi/lo split: g_v[b][h][l] -> g_vt[b][l][hi|lo]
// ---------------------------------------------------------------------------
__global__ __launch_bounds__(256) void transpose_split_kernel() {
    __shared__ float ts[64][65];
    int l0 = blockIdx.x * 64;
    int h0 = blockIdx.y * 64;
    int b  = blockIdx.z;
    int t  = threadIdx.x;
    int tl = t & 63;
    int tr = t >> 6;

    const float* vp = g_v + ((size_t)(b * HH + h0)) * LL + l0;
    #pragma unroll
    for (int i = 0; i < 16; i++) {
        int hh = tr + i * 4;
        ts[hh][tl] = vp[(size_t)hh * LL + tl];
    }
    __syncthreads();

    __nv_bfloat16* op = g_vt + ((size_t)b * LL + l0) * 2048;
    #pragma unroll
    for (int i = 0; i < 16; i++) {
        int ll = tr + i * 4;
        float x = ts[tl][ll];
        __nv_bfloat16 hi = __float2bfloat16(x);
        __nv_bfloat16 lo = __float2bfloat16(x - __bfloat162float(hi));
        op[(size_t)ll * 2048 + h0 + tl]        = hi;
        op[(size_t)ll * 2048 + 1024 + h0 + tl] = lo;
    }
}

// ---------------------------------------------------------------------------
// Kernel 3: tcgen05 split-bf16 GEMM, 4-stage ring, cp.async mainloop. PROVEN.
// ---------------------------------------------------------------------------
#define GM     128
#define GN     256
#define GK     64
#define NCHUNK 48
#define NSTG   4
#define STGSZ  (48 * 1024)
#define SBOFF  (16 * 1024)

#define SMB   (NSTG * STGSZ)
#define STM   (NSTG * STGSZ + 64)
#define SBIAS (NSTG * STGSZ + 128)
#define SMEM_TOTAL_G (NSTG * STGSZ + 128 + 1024)

#if HAS_TC
static constexpr uint32_t IDESC =
    (1u << 4) | (1u << 7) | (1u << 10) | ((GN / 8) << 17) | ((GM / 16) << 24);
#endif

__global__ void __launch_bounds__(256, 1)
gemm_kernel(const float* __restrict__ bias, float* __restrict__ out,
            const float* __restrict__ W) {
    extern __shared__ char smem[];
    int tid  = threadIdx.x;
    int l0 = blockIdx.x * GM;
    int o0 = blockIdx.y * GN;
    int b  = blockIdx.z;

#if HAS_TC
    uint32_t sb = s2u(smem);
    int wid  = tid >> 5;
    int lane = tid & 31;

    if (wid == 0) {
        asm volatile("tcgen05.alloc.cta_group::1.sync.aligned.shared::cta.b32 [%0], %1;"
                     :: "r"(sb + STM), "r"(256) : "memory");
    }
    if (tid == 0) {
        #pragma unroll
        for (int s = 0; s < NSTG; s++) MBAR_INIT(sb + SMB + s * 8, 1);
    }
    ((float*)(smem + SBIAS))[tid] = bias[o0 + tid];
    __syncthreads();
    uint32_t tmem;
    asm volatile("ld.shared.b32 %0, [%1];" : "=r"(tmem) : "r"(sb + STM));

    const __nv_bfloat16* vt = g_vt + (size_t)b * LL * 2048;

    int ar = tid >> 3, aq = tid & 7;

#define CPA_CHUNK(c, s)                                                       \
    do {                                                                      \
        int seg  = (c) >> 4;                                                  \
        int kc   = ((c) & 15) * GK;                                           \
        int aoff = (seg == 1) ? 1024 : 0;                                     \
        int boff = (seg == 2) ? 1024 : 0;                                     \
        const __nv_bfloat16* ap = vt + (size_t)l0 * 2048 + aoff + kc;         \
        const __nv_bfloat16* bp = g_ws + (size_t)o0 * 2048 + boff + kc;       \
        uint32_t As = sb + (s) * STGSZ;                                       \
        uint32_t Bs = As + SBOFF;                                             \
        _Pragma("unroll")                                                     \
        for (int i = 0; i < 4; i++) {                                         \
            int r = ar + i * 32;                                              \
            CPA16(As + SW128(r * 128 + aq * 16),                              \
                  ap + (size_t)r * 2048 + aq * 8);                            \
        }                                                                     \
        _Pragma("unroll")                                                     \
        for (int i = 0; i < 8; i++) {                                         \
            int r = ar + i * 32;                                              \
            CPA16(Bs + SW128(r * 128 + aq * 16),                              \
                  bp + (size_t)r * 2048 + aq * 8);                            \
        }                                                                     \
    } while (0)

    CPA_CHUNK(0, 0); CPA_COMMIT();
    CPA_CHUNK(1, 1); CPA_COMMIT();
    CPA_WAIT(0);
    asm volatile("fence.proxy.async.shared::cta;" ::: "memory");
    __syncthreads();

    uint32_t ph[NSTG] = {0, 0, 0, 0};

    for (int c = 0; c < NCHUNK; c++) {
        int s = c & (NSTG - 1);
        if (wid == 0) {
            if (elect1()) {
                uint64_t ad = mkdesc(sb + s * STGSZ);
                uint64_t bd = mkdesc(sb + s * STGSZ + SBOFF);
                #pragma unroll
                for (int k = 0; k < 4; k++)
                    mma_ss_f16(tmem, ad + k * 2, bd + k * 2, IDESC,
                               (c > 0 || k > 0) ? 1u : 0u);
                TC_COMMIT(sb + SMB + s * 8);
            }
        }
        if (c + 2 < NCHUNK) {
            int ws = (c + 2) & (NSTG - 1);
            if (c >= 2) {
                WAIT_PARITY(sb + SMB + ws * 8, ph[ws]);
                ph[ws] ^= 1;
            }
            CPA_CHUNK(c + 2, ws);
            CPA_COMMIT();
            CPA_WAIT(1);
        } else {
            CPA_WAIT(0);
        }
        asm volatile("fence.proxy.async.shared::cta;" ::: "memory");
        __syncthreads();
    }
    WAIT_PARITY(sb + SMB + 3 * 8, ph[3]);
    asm volatile("tcgen05.fence::after_thread_sync;" ::: "memory");

    int sub  = wid & 3;
    int half = wid >> 2;
    int lg   = l0 + sub * 32 + lane;
    const float* bs = (const float*)(smem + SBIAS);
    #pragma unroll
    for (int it = 0; it < 4; it++) {
        int cb = half * 128 + it * 32;
        uint32_t r[32];
        LDTM_X32(r, tmem + cb);
        asm volatile("tcgen05.wait::ld.sync.aligned;" ::: "memory");
        float* op = out + ((size_t)(b * HH + o0 + cb)) * LL + lg;
        #pragma unroll
        for (int j = 0; j < 32; j++)
            op[(size_t)j * LL] = __uint_as_float(r[j]) + bs[cb + j];
    }
    __syncthreads();
    if (wid == 0) {
        asm volatile("tcgen05.relinquish_alloc_permit.cta_group::1.sync.aligned;");
        asm volatile("tcgen05.dealloc.cta_group::1.sync.aligned.b32 %0, %1;"
                     :: "r"(tmem), "r"(256));
    }
#undef CPA_CHUNK

#else  // SIMT fp32 fallback
    float (*Ws)[GN]  = (float (*)[GN])(smem);
    float (*Vs)[128] = (float (*)[128])(smem + 16 * GN * 4);

    int tx = tid & 15;
    int ty = tid >> 4;

    float acc[16][8];
    #pragma unroll
    for (int i = 0; i < 16; i++)
        #pragma unroll
        for (int j = 0; j < 8; j++) acc[i][j] = 0.0f;

    const float* vbase = g_v + ((size_t)b * HH) * LL + l0;

    for (int kb = 0; kb < HH; kb += 16) {
        #pragma unroll
        for (int i = 0; i < 16; i++) {
            int idx = tid + i * 256;
            int kk  = idx & 15;
            int mm  = idx >> 4;
            Ws[kk][mm] = W[(size_t)(o0 + mm) * HH + kb + kk];
        }
        #pragma unroll
        for (int i = 0; i < 8; i++) {
            int idx = tid + i * 256;
            int ll  = idx & 127;
            int kk  = idx >> 7;
            Vs[kk][ll] = vbase[(size_t)(kb + kk) * LL + ll];
        }
        __syncthreads();

        #pragma unroll
        for (int kk = 0; kk < 16; kk++) {
            float bf[8];
            #pragma unroll
            for (int j = 0; j < 8; j++) bf[j] = Vs[kk][tx * 8 + j];
            #pragma unroll
            for (int i = 0; i < 16; i++) {
                float a = Ws[kk][ty * 16 + i];
                #pragma unroll
                for (int j = 0; j < 8; j++)
                    acc[i][j] += a * bf[j];
            }
        }
        __syncthreads();
    }

    #pragma unroll
    for (int i = 0; i < 16; i++) {
        int o = o0 + ty * 16 + i;
        float bb = bias[o];
        float* op = out + ((size_t)(b * HH + o)) * LL + l0 + tx * 8;
        #pragma unroll
        for (int j = 0; j < 8; j++)
            op[j] = acc[i][j] + bb;
    }
#endif
}

// ---------------------------------------------------------------------------
extern "C" void kernel_launch(void* const* d_in, const int* in_sizes, int n_in,
                              void* d_out, int out_size) {
    const float* u  = (const float*)d_in[0];
    const float* k0 = (const float*)d_in[1];
    const float* k1 = (const float*)d_in[2];
    const float* k2 = (const float*)d_in[3];
    const float* k3 = (const float*)d_in[4];
    const float* D  = (const float*)d_in[5];
    const float* W  = (const float*)d_in[6];
    const float* b  = (const float*)d_in[7];
    float* out = (float*)d_out;

    build_filter_kernel<<<HH, 128>>>(k0, k1, k2, k3, W);

    usplit_kernel<<<BB * HH, 256>>>(u);

    cudaFuncSetAttribute(toeplitz_fir_kernel,
                         cudaFuncAttributeMaxDynamicSharedMemorySize, SMEM_TOTAL_T);
    dim3 gf(2, HH, 1);
    toeplitz_fir_kernel<<<gf, 256, SMEM_TOTAL_T>>>(u, D);

    dim3 gt(LL / 64, HH / 64, BB);
    transpose_split_kernel<<<gt, 256>>>();

    cudaFuncSetAttribute(gemm_kernel, cudaFuncAttributeMaxDynamicSharedMemorySize,
                         SMEM_TOTAL_G);
    dim3 g3(LL / GM, HH / GN, BB);
    gemm_kernel<<<g3, 256, SMEM_TOTAL_G>>>(b, out, W);
}

// round 15
// speedup vs baseline: 1.2784x; 1.0697x over previous
#include <cuda_runtime.h>
#include <cuda_bf16.h>
#include <math.h>
#include <stdint.h>

#define HH   1024
#define LL   8192
#define BB   4
#define KDIM 64
#define KTOT 512

#if defined(__CUDA_ARCH_FEAT_SM103_ALL) || defined(__CUDA_ARCH_FEAT_SM100_ALL)
#define HAS_TC 1
#else
#define HAS_TC 0
#endif

// scratch
__device__ float g_filt[HH * KTOT];
__device__ float g_v[(size_t)BB * HH * LL];
__device__ __align__(256) __nv_bfloat16 g_vt[(size_t)BB * LL * 2048]; // [b][l][hi|lo]
__device__ __align__(256) __nv_bfloat16 g_ws[(size_t)HH * 2048];      // [o][hi|lo]
// u split with 512-elem zero halo per (b,h) row: row stride 8704
#define UROW 8704
__device__ __align__(256) __nv_bfloat16 g_uh[(size_t)BB * HH * UROW];
__device__ __align__(256) __nv_bfloat16 g_ul[(size_t)BB * HH * UROW];

// ---------------------------------------------------------------------------
// PTX helpers (guarded)
// ---------------------------------------------------------------------------
#if HAS_TC
__device__ __forceinline__ uint32_t s2u(const void* p) {
    uint32_t a;
    asm("{ .reg .u64 t; cvta.to.shared.u64 t, %1; cvt.u32.u64 %0, t; }"
        : "=r"(a) : "l"(p));
    return a;
}
__device__ __forceinline__ uint32_t elect1() {
    uint32_t p;
    asm volatile("{\n\t.reg .pred p;\n\telect.sync _|p, 0xFFFFFFFF;\n\t"
                 "selp.b32 %0, 1, 0, p;\n\t}" : "=r"(p));
    return p;
}
#define SW128(x) ((x) ^ (((x) >> 3) & 0x70))

static constexpr uint64_t DESC_BASE =
    (2ull << 61) | (1ull << 46) | (64ull << 32) | (1ull << 16); // SW128, LBO=1, SBO=64
__device__ __forceinline__ uint64_t mkdesc(uint32_t a) {
    return DESC_BASE | ((uint64_t)(a >> 4) & 0x3FFF);
}

__device__ __forceinline__ void mma_ss_f16(uint32_t d, uint64_t a, uint64_t b,
                                           uint32_t id, uint32_t en) {
    asm volatile("{\n\t.reg .pred p;\n\tsetp.ne.u32 p, %5, 0;\n\t"
                 "tcgen05.mma.cta_group::1.kind::f16 [%0], %1, %2, %3, {%4,%4,%4,%4}, p;\n\t}"
                 :: "r"(d), "l"(a), "l"(b), "r"(id), "r"(0u), "r"(en) : "memory");
}

#define MBAR_INIT(a, c) \
    asm volatile("mbarrier.init.shared.b64 [%0], %1;" :: "r"(a), "r"(c) : "memory")
#define TC_COMMIT(a) \
    asm volatile("tcgen05.commit.cta_group::1.mbarrier::arrive::one.shared::cluster.b64 [%0];" \
                 :: "r"(a) : "memory")
#define WAIT_PARITY(mb, ph) do {                                              \
    asm volatile("{\n\t.reg .pred P1;\n\t"                                    \
        "WL_%=:\n\t"                                                          \
        "mbarrier.try_wait.parity.acquire.cta.shared::cta.b64 P1, [%0], %1, 0x989680;\n\t" \
        "@P1 bra.uni WD_%=;\n\t"                                              \
        "bra.uni WL_%=;\n\t"                                                  \
        "WD_%=:\n\t}" :: "r"(mb), "r"(ph) : "memory");                        \
} while (0)

#define LDTM_X32(r, a)                                                        \
    asm volatile("tcgen05.ld.sync.aligned.32x32b.x32.b32 "                    \
        "{%0, %1, %2, %3, %4, %5, %6, %7, "                                   \
        " %8, %9, %10, %11, %12, %13, %14, %15, "                             \
        " %16, %17, %18, %19, %20, %21, %22, %23, "                           \
        " %24, %25, %26, %27, %28, %29, %30, %31}, [%32];"                    \
        : "=r"((r)[0]),  "=r"((r)[1]),  "=r"((r)[2]),  "=r"((r)[3]),          \
          "=r"((r)[4]),  "=r"((r)[5]),  "=r"((r)[6]),  "=r"((r)[7]),          \
          "=r"((r)[8]),  "=r"((r)[9]),  "=r"((r)[10]), "=r"((r)[11]),         \
          "=r"((r)[12]), "=r"((r)[13]), "=r"((r)[14]), "=r"((r)[15]),         \
          "=r"((r)[16]), "=r"((r)[17]), "=r"((r)[18]), "=r"((r)[19]),         \
          "=r"((r)[20]), "=r"((r)[21]), "=r"((r)[22]), "=r"((r)[23]),         \
          "=r"((r)[24]), "=r"((r)[25]), "=r"((r)[26]), "=r"((r)[27]),         \
          "=r"((r)[28]), "=r"((r)[29]), "=r"((r)[30]), "=r"((r)[31])          \
        : "r"(a))

#define CPA16(dst, src) \
    asm volatile("cp.async.cg.shared.global [%0], [%1], 16;" \
                 :: "r"(dst), "l"(src) : "memory")
#define CPA_COMMIT() asm volatile("cp.async.commit_group;" ::: "memory")
#define CPA_WAIT(n)  asm volatile("cp.async.wait_group %0;" :: "n"(n) : "memory")
#endif // HAS_TC

// ---------------------------------------------------------------------------
// Kernel 1: assemble multi-scale filter + normalize, AND split W row o = h.
// ---------------------------------------------------------------------------
__global__ void build_filter_kernel(const float* __restrict__ k0,
                                    const float* __restrict__ k1,
                                    const float* __restrict__ k2,
                                    const float* __restrict__ k3,
                                    const float* __restrict__ W) {
    int h   = blockIdx.x;
    int tid = threadIdx.x;             // 128 threads
    const float* ks0 = k0 + h * KDIM;
    const float* ks1 = k1 + h * KDIM;
    const float* ks2 = k2 + h * KDIM;
    const float* ks3 = k3 + h * KDIM;

    #pragma unroll
    for (int rr = 0; rr < 8; rr++) {
        int j = tid + rr * 128;
        float x = W[(size_t)h * HH + j];
        __nv_bfloat16 hi = __float2bfloat16(x);
        __nv_bfloat16 lo = __float2bfloat16(x - __bfloat162float(hi));
        g_ws[(size_t)h * 2048 + j]        = hi;
        g_ws[(size_t)h * 2048 + 1024 + j] = lo;
    }

    __shared__ float red[128];
    float vals[4];
    float ss = 0.0f;

    #pragma unroll
    for (int r = 0; r < 4; r++) {
        int t = tid + r * 128;
        float acc = 0.0f;
        #pragma unroll
        for (int i = 0; i < 4; i++) {
            int Li = KDIM << i;
            if (t < Li) {
                float coord = (t + 0.5f) / (float)(1 << i) - 0.5f;
                coord = fminf(fmaxf(coord, 0.0f), (float)(KDIM - 1));
                int   lo = (int)floorf(coord);
                int   hi = min(lo + 1, KDIM - 1);
                float w  = coord - (float)lo;
                const float* kp = (i == 0) ? ks0 : (i == 1) ? ks1 : (i == 2) ? ks2 : ks3;
                float v = kp[lo] * (1.0f - w) + kp[hi] * w;
                acc += v * (float)(1 << (3 - i));
            }
        }
        vals[r] = acc;
        ss += acc * acc;
    }

    red[tid] = ss;
    __syncthreads();
    for (int s = 64; s > 0; s >>= 1) {
        if (tid < s) red[tid] += red[tid + s];
        __syncthreads();
    }
    float inv = 1.0f / sqrtf(red[0]);

    #pragma unroll
    for (int r = 0; r < 4; r++) {
        int t = tid + r * 128;
        g_filt[h * KTOT + t] = vals[r] * inv;
    }
}

// ---------------------------------------------------------------------------
// Kernel 1b: u -> bf16 hi/lo split with 512-entry zero halo per (b,h) row
// ---------------------------------------------------------------------------
__global__ __launch_bounds__(256) void usplit_kernel(const float* __restrict__ u) {
    int bh  = blockIdx.x;               // 0..4095
    int tid = threadIdx.x;
    size_t src = (size_t)bh * LL;
    size_t dst = (size_t)bh * UROW;

    if (tid < 256) {
        ((uint32_t*)(g_uh + dst))[tid] = 0u;
        ((uint32_t*)(g_ul + dst))[tid] = 0u;
    }
    #pragma unroll
    for (int i = 0; i < 16; i++) {
        int l2 = (tid + i * 256) * 2;
        float2 x = *reinterpret_cast<const float2*>(u + src + l2);
        __nv_bfloat16 h0 = __float2bfloat16(x.x);
        __nv_bfloat16 l0 = __float2bfloat16(x.x - __bfloat162float(h0));
        __nv_bfloat16 h1 = __float2bfloat16(x.y);
        __nv_bfloat16 l1 = __float2bfloat16(x.y - __bfloat162float(h1));
        uint32_t ph = (uint32_t)*(uint16_t*)&h0 | ((uint32_t)*(uint16_t*)&h1 << 16);
        uint32_t pl = (uint32_t)*(uint16_t*)&l0 | ((uint32_t)*(uint16_t*)&l1 << 16);
        *(uint32_t*)(g_uh + dst + 512 + l2) = ph;
        *(uint32_t*)(g_ul + dst + 512 + l2) = pl;
    }
}

// ---------------------------------------------------------------------------
// Kernel 2: Toeplitz FIR on tensor cores (ROUND-12 PROVEN VERSION, untouched).
// ---------------------------------------------------------------------------
#define TSTG    0x10000              // 64KB per stage
#define TH_OFF  0
#define TL_OFF  0x4000
#define UH_OFF  0x8000
#define UL_OFF  0xC000
#define TKR     (3 * TSTG)           // kr arrays base
#define TKF     (TKR + 0x1800)       // fp32 filter copy (2KB)
#define TMB     (TKR + 0x2000)       // 3 mbarriers
#define TTM     (TKR + 0x2040)       // tmem ptr
#define SMEM_TOTAL_T (TKR + 0x2080)

#if HAS_TC
static constexpr uint32_t IDESC_T =
    (1u << 4) | (1u << 7) | (1u << 10) | ((128 / 8) << 17) | ((128 / 16) << 24);
#endif

__global__ void __launch_bounds__(256, 1)
toeplitz_fir_kernel(const float* __restrict__ u, const float* __restrict__ D) {
    extern __shared__ char smem[];
    int tid = threadIdx.x;
    int nh  = blockIdx.x;               // 0..1  (n half)
    int h   = blockIdx.y;               // 0..1023

#if HAS_TC
    uint32_t sb = s2u(smem);
    int wid  = tid >> 5;
    int lane = tid & 31;

    if (wid == 0) {
        asm volatile("tcgen05.alloc.cta_group::1.sync.aligned.shared::cta.b32 [%0], %1;"
                     :: "r"(sb + TTM), "r"(128) : "memory");
    }
    if (tid == 0) {
        #pragma unroll
        for (int s = 0; s < 3; s++) MBAR_INIT(sb + TMB + s * 8, 1);
    }

    // filter fp32 copy
    float* kf = (float*)(smem + TKF);
    if (tid < 128) {
        *reinterpret_cast<float4*>(kf + tid * 4) =
            *reinterpret_cast<const float4*>(g_filt + h * KTOT + tid * 4);
    }
    __syncthreads();

    // kr storage: kr[x] (x in [0,768)) = (x in [128,640)) ? k[639-x] : 0
    __nv_bfloat16* kr0h = (__nv_bfloat16*)(smem + TKR);
    __nv_bfloat16* kr0l = (__nv_bfloat16*)(smem + TKR + 0x600);
    __nv_bfloat16* kr1h = (__nv_bfloat16*)(smem + TKR + 0xC00);
    __nv_bfloat16* kr1l = (__nv_bfloat16*)(smem + TKR + 0x1200);
    for (int x = tid; x < 768; x += 256) {
        float v = (x >= 128 && x < 640) ? kf[639 - x] : 0.0f;
        __nv_bfloat16 hi = __float2bfloat16(v);
        __nv_bfloat16 lo = __float2bfloat16(v - __bfloat162float(hi));
        kr0h[x] = hi; kr0l[x] = lo;
    }
    __syncthreads();
    for (int x = tid; x < 768; x += 256) {
        __nv_bfloat16 z; *(uint16_t*)&z = 0;
        kr1h[x] = (x + 1 < 768) ? kr0h[x + 1] : z;
        kr1l[x] = (x + 1 < 768) ? kr0l[x + 1] : z;
    }
    __syncthreads();

    uint32_t tmem;
    asm volatile("ld.shared.b32 %0, [%1];" : "=r"(tmem) : "r"(sb + TTM));

    int un  = tid >> 1;
    int uq  = (tid & 1) * 4;
    int nng = nh * 128 + un;
    int ubb = nng >> 6;
    int utl = nng & 63;
    size_t urow = ((size_t)(ubb * HH + h)) * UROW + utl * 128;
    int ti = tid >> 1;
    int tjb = (tid & 1) * 32;

    const uint32_t* kr0h32 = (const uint32_t*)kr0h;
    const uint32_t* kr0l32 = (const uint32_t*)kr0l;
    const uint32_t* kr1h32 = (const uint32_t*)kr1h;
    const uint32_t* kr1l32 = (const uint32_t*)kr1l;

#define FILL_CHUNK(c, s)                                                      \
    do {                                                                      \
        const __nv_bfloat16* srh = g_uh + urow + 64 * (c);                    \
        const __nv_bfloat16* srl = g_ul + urow + 64 * (c);                    \
        uint32_t uhd = sb + (s) * TSTG + UH_OFF;                              \
        uint32_t uld = sb + (s) * TSTG + UL_OFF;                              \
        _Pragma("unroll")                                                     \
        for (int q = 0; q < 4; q++) {                                         \
            uint32_t so = SW128(un * 128 + (uq + q) * 16);                    \
            CPA16(uhd + so, srh + (uq + q) * 8);                              \
            CPA16(uld + so, srl + (uq + q) * 8);                              \
        }                                                                     \
        uint32_t thd = sb + (s) * TSTG + TH_OFF;                              \
        uint32_t tld = sb + (s) * TSTG + TL_OFF;                              \
        _Pragma("unroll")                                                     \
        for (int o = 0; o < 4; o++) {                                         \
            int js0 = tjb + 8 * o;                                            \
            int x0  = 128 + js0 + 64 * (c) - ti - 1;                          \
            const uint32_t* sh; const uint32_t* sl;                           \
            if (x0 & 1) { int w = (x0 - 1) >> 1; sh = kr1h32 + w; sl = kr1l32 + w; } \
            else        { int w = x0 >> 1;       sh = kr0h32 + w; sl = kr0l32 + w; } \
            uint4 vh = make_uint4(sh[0], sh[1], sh[2], sh[3]);                \
            uint4 vl = make_uint4(sl[0], sl[1], sl[2], sl[3]);                \
            uint32_t dsto = SW128(ti * 128 + js0 * 2);                        \
            *(uint4*)(smem + (thd - sb) + dsto) = vh;                         \
            *(uint4*)(smem + (tld - sb) + dsto) = vl;                         \
        }                                                                     \
    } while (0)

    FILL_CHUNK(0, 0); CPA_COMMIT();
    FILL_CHUNK(1, 1); CPA_COMMIT();
    CPA_WAIT(0);
    asm volatile("fence.proxy.async.shared::cta;" ::: "memory");
    __syncthreads();

    uint32_t ph[3] = {0, 0, 0};

    for (int c = 0; c < 10; c++) {
        int s = c - (c / 3) * 3;
        if (wid == 0) {
            if (elect1()) {
                uint64_t ThD = mkdesc(sb + s * TSTG + TH_OFF);
                uint64_t TlD = mkdesc(sb + s * TSTG + TL_OFF);
                uint64_t UhD = mkdesc(sb + s * TSTG + UH_OFF);
                uint64_t UlD = mkdesc(sb + s * TSTG + UL_OFF);
                #pragma unroll
                for (int k = 0; k < 4; k++)
                    mma_ss_f16(tmem, ThD + k * 2, UhD + k * 2, IDESC_T,
                               (c > 0 || k > 0) ? 1u : 0u);
                #pragma unroll
                for (int k = 0; k < 4; k++)
                    mma_ss_f16(tmem, ThD + k * 2, UlD + k * 2, IDESC_T, 1u);
                #pragma unroll
                for (int k = 0; k < 4; k++)
                    mma_ss_f16(tmem, TlD + k * 2, UhD + k * 2, IDESC_T, 1u);
                TC_COMMIT(sb + TMB + s * 8);
            }
        }
        if (c + 2 < 10) {
            int ws = (c + 2) - ((c + 2) / 3) * 3;
            if (c >= 1) {
                WAIT_PARITY(sb + TMB + ws * 8, ph[ws]);
                ph[ws] ^= 1;
            }
            FILL_CHUNK(c + 2, ws);
            CPA_COMMIT();
            CPA_WAIT(1);
        } else {
            CPA_WAIT(0);
        }
        asm volatile("fence.proxy.async.shared::cta;" ::: "memory");
        __syncthreads();
    }
    WAIT_PARITY(sb + TMB + 0 * 8, ph[0]);
    asm volatile("tcgen05.fence::after_thread_sync;" ::: "memory");

    float Dh = D[h];
    const float iS2 = 0.70710678118654752440f;
    int sub   = wid & 3;
    int chalf = wid >> 2;
    int il    = sub * 32 + lane;
    #pragma unroll
    for (int it = 0; it < 2; it++) {
        int cb = chalf * 64 + it * 32;
        uint32_t r[32];
        LDTM_X32(r, tmem + cb);
        asm volatile("tcgen05.wait::ld.sync.aligned;" ::: "memory");
        #pragma unroll
        for (int j = 0; j < 32; j++) {
            int nn = nh * 128 + cb + j;
            int bb = nn >> 6;
            int tl = nn & 63;
            int l  = tl * 128 + il;
            size_t off = ((size_t)(bb * HH + h)) * LL + l;
            float x = __uint_as_float(r[j]) + Dh * u[off];
            g_v[off] = 0.5f * x * (1.0f + erff(x * iS2));
        }
    }
    __syncthreads();
    if (wid == 0) {
        asm volatile("tcgen05.relinquish_alloc_permit.cta_group::1.sync.aligned;");
        asm volatile("tcgen05.dealloc.cta_group::1.sync.aligned.b32 %0, %1;"
                     :: "r"(tmem), "r"(128));
    }
#undef FILL_CHUNK

#else  // naive fallback (baseline-family cubin; not used on sm_103a)
    float Dh = D[h];
    const float iS2 = 0.70710678118654752440f;
    for (int idx = tid; idx < 128 * 128; idx += 256) {
        int np = idx >> 7;
        int i  = idx & 127;
        int nn = nh * 128 + np;
        int bb = nn >> 6;
        int tl = nn & 63;
        int l  = tl * 128 + i;
        const float* up = u + ((size_t)(bb * HH + h)) * LL;
        float acc = 0.0f;
        for (int t = 0; t < KTOT; t++) {
            int li = l - t;
            if (li >= 0) acc += g_filt[h * KTOT + t] * up[li];
        }
        float x = acc + Dh * up[l];
        g_v[((size_t)(bb * HH + h)) * LL + l] = 0.5f * x * (1.0f + erff(x * iS2));
    }
#endif
}

// ---------------------------------------------------------------------------
// Kernel 2b: transpose + bf16 hi/lo split: g_v[b][h][l] -> g_vt[b][l][hi|lo]
// ---------------------------------------------------------------------------
__global__ __launch_bounds__(256) void transpose_split_kernel() {
    __shared__ float ts[64][65];
    int l0 = blockIdx.x * 64;
    int h0 = blockIdx.y * 64;
    int b  = blockIdx.z;
    int t  = threadIdx.x;
    int tl = t & 63;
    int tr = t >> 6;

    const float* vp = g_v + ((size_t)(b * HH + h0)) * LL + l0;
    #pragma unroll
    for (int i = 0; i < 16; i++) {
        int hh = tr + i * 4;
        ts[hh][tl] = vp[(size_t)hh * LL + tl];
    }
    __syncthreads();

    __nv_bfloat16* op = g_vt + ((size_t)b * LL + l0) * 2048;
    #pragma unroll
    for (int i = 0; i < 16; i++) {
        int ll = tr + i * 4;
        float x = ts[tl][ll];
        __nv_bfloat16 hi = __float2bfloat16(x);
        __nv_bfloat16 lo = __float2bfloat16(x - __bfloat162float(hi));
        op[(size_t)ll * 2048 + h0 + tl]        = hi;
        op[(size_t)ll * 2048 + 1024 + h0 + tl] = lo;
    }
}

// ---------------------------------------------------------------------------
// Kernel 3: tcgen05 split-bf16 GEMM, M=256 (two M=128 dispatch sets share B),
// 3-stage 64KB ring, cp.async mainloop. Halves L2 traffic vs M=128.
// ---------------------------------------------------------------------------
#define GM     256
#define GN     256
#define GK     64
#define NCHUNK 48
#define NSTG   3
#define STGSZ  (64 * 1024)          // A 32KB + B 32KB
#define SBOFF  (32 * 1024)

#define SMB   (NSTG * STGSZ)
#define STM   (NSTG * STGSZ + 64)
#define SBIAS (NSTG * STGSZ + 128)
#define SMEM_TOTAL_G (NSTG * STGSZ + 128 + 1024)

#if HAS_TC
static constexpr uint32_t IDESC =
    (1u << 4) | (1u << 7) | (1u << 10) | ((GN / 8) << 17) | ((128 / 16) << 24);
#endif

__global__ void __launch_bounds__(256, 1)
gemm_kernel(const float* __restrict__ bias, float* __restrict__ out,
            const float* __restrict__ W) {
    extern __shared__ char smem[];
    int tid  = threadIdx.x;
    int l0 = blockIdx.x * GM;
    int o0 = blockIdx.y * GN;
    int b  = blockIdx.z;

#if HAS_TC
    uint32_t sb = s2u(smem);
    int wid  = tid >> 5;
    int lane = tid & 31;

    if (wid == 0) {
        asm volatile("tcgen05.alloc.cta_group::1.sync.aligned.shared::cta.b32 [%0], %1;"
                     :: "r"(sb + STM), "r"(512) : "memory");
    }
    if (tid == 0) {
        #pragma unroll
        for (int s = 0; s < NSTG; s++) MBAR_INIT(sb + SMB + s * 8, 1);
    }
    ((float*)(smem + SBIAS))[tid] = bias[o0 + tid];
    __syncthreads();
    uint32_t tmem;
    asm volatile("ld.shared.b32 %0, [%1];" : "=r"(tmem) : "r"(sb + STM));

    const __nv_bfloat16* vt = g_vt + (size_t)b * LL * 2048;

    int ar = tid >> 3, aq = tid & 7;   // ar 0..31, rows r = ar + i*32

#define CPA_CHUNK(c, s)                                                       \
    do {                                                                      \
        int seg  = (c) >> 4;                                                  \
        int kc   = ((c) & 15) * GK;                                           \
        int aoff = (seg == 1) ? 1024 : 0;                                     \
        int boff = (seg == 2) ? 1024 : 0;                                     \
        const __nv_bfloat16* ap = vt + (size_t)l0 * 2048 + aoff + kc;         \
        const __nv_bfloat16* bp = g_ws + (size_t)o0 * 2048 + boff + kc;       \
        uint32_t As = sb + (s) * STGSZ;                                       \
        uint32_t Bs = As + SBOFF;                                             \
        _Pragma("unroll")                                                     \
        for (int i = 0; i < 8; i++) {                                         \
            int r = ar + i * 32;                                              \
            CPA16(As + SW128(r * 128 + aq * 16),                              \
                  ap + (size_t)r * 2048 + aq * 8);                            \
        }                                                                     \
        _Pragma("unroll")                                                     \
        for (int i = 0; i < 8; i++) {                                         \
            int r = ar + i * 32;                                              \
            CPA16(Bs + SW128(r * 128 + aq * 16),                              \
                  bp + (size_t)r * 2048 + aq * 8);                            \
        }                                                                     \
    } while (0)

    CPA_CHUNK(0, 0); CPA_COMMIT();
    CPA_CHUNK(1, 1); CPA_COMMIT();
    CPA_WAIT(0);
    asm volatile("fence.proxy.async.shared::cta;" ::: "memory");
    __syncthreads();

    uint32_t ph[NSTG] = {0, 0, 0};

    for (int c = 0; c < NCHUNK; c++) {
        int s = c - (c / 3) * 3;
        if (wid == 0) {
            if (elect1()) {
                uint32_t Abase = sb + s * STGSZ;
                uint64_t bd    = mkdesc(Abase + SBOFF);
                uint64_t ad0   = mkdesc(Abase);
                uint64_t ad1   = mkdesc(Abase + 16384);   // A rows 128..255
                #pragma unroll
                for (int k = 0; k < 4; k++) {
                    uint32_t en = (c > 0 || k > 0) ? 1u : 0u;
                    mma_ss_f16(tmem,       ad0 + k * 2, bd + k * 2, IDESC, en);
                    mma_ss_f16(tmem + 256, ad1 + k * 2, bd + k * 2, IDESC, en);
                }
                TC_COMMIT(sb + SMB + s * 8);
            }
        }
        if (c + 2 < NCHUNK) {
            int ws = (c + 2) - ((c + 2) / 3) * 3;
            if (c >= 1) {
                WAIT_PARITY(sb + SMB + ws * 8, ph[ws]);
                ph[ws] ^= 1;
            }
            CPA_CHUNK(c + 2, ws);
            CPA_COMMIT();
            CPA_WAIT(1);
        } else {
            CPA_WAIT(0);
        }
        asm volatile("fence.proxy.async.shared::cta;" ::: "memory");
        __syncthreads();
    }
    // last chunk 47 -> stage 47%3 = 2
    WAIT_PARITY(sb + SMB + 2 * 8, ph[2]);
    asm volatile("tcgen05.fence::after_thread_sync;" ::: "memory");

    // epilogue: warps 0-3 -> M half0 (TMEM cols 0-255), warps 4-7 -> half1
    int sub  = wid & 3;
    int half = wid >> 2;
    int lg   = l0 + half * 128 + sub * 32 + lane;
    const float* bs = (const float*)(smem + SBIAS);
    #pragma unroll
    for (int it = 0; it < 8; it++) {
        int cb = it * 32;
        uint32_t r[32];
        LDTM_X32(r, tmem + half * 256 + cb);
        asm volatile("tcgen05.wait::ld.sync.aligned;" ::: "memory");
        float* op = out + ((size_t)(b * HH + o0 + cb)) * LL + lg;
        #pragma unroll
        for (int j = 0; j < 32; j++)
            op[(size_t)j * LL] = __uint_as_float(r[j]) + bs[cb + j];
    }
    __syncthreads();
    if (wid == 0) {
        asm volatile("tcgen05.relinquish_alloc_permit.cta_group::1.sync.aligned;");
        asm volatile("tcgen05.dealloc.cta_group::1.sync.aligned.b32 %0, %1;"
                     :: "r"(tmem), "r"(512));
    }
#undef CPA_CHUNK

#else  // SIMT fp32 fallback: two passes of 128 l x 256 o
    float (*Ws)[GN]  = (float (*)[GN])(smem);
    float (*Vs)[128] = (float (*)[128])(smem + 16 * GN * 4);

    int tx = tid & 15;
    int ty = tid >> 4;

    for (int pass = 0; pass < 2; pass++) {
        int lp = l0 + pass * 128;
        float acc[16][8];
        #pragma unroll
        for (int i = 0; i < 16; i++)
            #pragma unroll
            for (int j = 0; j < 8; j++) acc[i][j] = 0.0f;

        const float* vbase = g_v + ((size_t)b * HH) * LL + lp;

        for (int kb = 0; kb < HH; kb += 16) {
            #pragma unroll
            for (int i = 0; i < 16; i++) {
                int idx = tid + i * 256;
                int kk  = idx & 15;
                int mm  = idx >> 4;
                Ws[kk][mm] = W[(size_t)(o0 + mm) * HH + kb + kk];
            }
            #pragma unroll
            for (int i = 0; i < 8; i++) {
                int idx = tid + i * 256;
                int ll  = idx & 127;
                int kk  = idx >> 7;
                Vs[kk][ll] = vbase[(size_t)(kb + kk) * LL + ll];
            }
            __syncthreads();

            #pragma unroll
            for (int kk = 0; kk < 16; kk++) {
                float bf[8];
                #pragma unroll
                for (int j = 0; j < 8; j++) bf[j] = Vs[kk][tx * 8 + j];
                #pragma unroll
                for (int i = 0; i < 16; i++) {
                    float a = Ws[kk][ty * 16 + i];
                    #pragma unroll
                    for (int j = 0; j < 8; j++)
                        acc[i][j] += a * bf[j];
                }
            }
            __syncthreads();
        }

        #pragma unroll
        for (int i = 0; i < 16; i++) {
            int o = o0 + ty * 16 + i;
            float bb = bias[o];
            float* op = out + ((size_t)(b * HH + o)) * LL + lp + tx * 8;
            #pragma unroll
            for (int j = 0; j < 8; j++)
                op[j] = acc[i][j] + bb;
        }
        __syncthreads();
    }
#endif
}

// ---------------------------------------------------------------------------
extern "C" void kernel_launch(void* const* d_in, const int* in_sizes, int n_in,
                              void* d_out, int out_size) {
    const float* u  = (const float*)d_in[0];
    const float* k0 = (const float*)d_in[1];
    const float* k1 = (const float*)d_in[2];
    const float* k2 = (const float*)d_in[3];
    const float* k3 = (const float*)d_in[4];
    const float* D  = (const float*)d_in[5];
    const float* W  = (const float*)d_in[6];
    const float* b  = (const float*)d_in[7];
    float* out = (float*)d_out;

    build_filter_kernel<<<HH, 128>>>(k0, k1, k2, k3, W);

    usplit_kernel<<<BB * HH, 256>>>(u);

    cudaFuncSetAttribute(toeplitz_fir_kernel,
                         cudaFuncAttributeMaxDynamicSharedMemorySize, SMEM_TOTAL_T);
    dim3 gf(2, HH, 1);
    toeplitz_fir_kernel<<<gf, 256, SMEM_TOTAL_T>>>(u, D);

    dim3 gt(LL / 64, HH / 64, BB);
    transpose_split_kernel<<<gt, 256>>>();

    cudaFuncSetAttribute(gemm_kernel, cudaFuncAttributeMaxDynamicSharedMemorySize,
                         SMEM_TOTAL_G);
    dim3 g3(LL / GM, HH / GN, BB);
    gemm_kernel<<<g3, 256, SMEM_TOTAL_G>>>(b, out, W);
}